// round 7
// baseline (speedup 1.0000x reference)
#include <cuda_runtime.h>

#define TT 512
#define BB 128
#define EE 128
#define HH 256
#define MM 1024
#define CC 5

// Scratch (static device globals — no allocation allowed).
// xproj padded by 512 floats so the per-step prefetch can read one row past the end.
__device__ float g_xproj[BB * TT * HH + 512];
__device__ float g_hn[BB * HH];
__device__ float g_relu1[BB * MM];

// ---------------------------------------------------------------------------
// f32x2 packed-FMA helpers (Blackwell FFMA2 path; ptxas won't auto-fuse)
// ---------------------------------------------------------------------------
__device__ __forceinline__ void fma2(unsigned long long& acc,
                                     unsigned long long a,
                                     unsigned long long b) {
    asm("fma.rn.f32x2 %0, %1, %2, %0;" : "+l"(acc) : "l"(a), "l"(b));
}
__device__ __forceinline__ float red2(unsigned long long a) {
    float lo, hi;
    asm("mov.b64 {%0, %1}, %2;" : "=f"(lo), "=f"(hi) : "l"(a));
    return lo + hi;
}
__device__ __forceinline__ float tanh_fast(float x) {
    // (e^{2x}-1)/(e^{2x}+1), clamped so __expf never overflows. abs err ~1e-6.
    float xc = fminf(fmaxf(x, -9.0f), 9.0f);
    float e = __expf(2.0f * xc);
    return __fdividef(e - 1.0f, e + 1.0f);
}

// ---------------------------------------------------------------------------
// Kernel 1: xproj[b,t,j] = emb[x[b,t]] . W_ih[j,:] + b_ih[j] + b_hh[j]
// grid (8 t-tiles of 64, 128 b), 256 thr. Fully-inactive tiles early-exit.
// Thread tile: 8 tokens x 8 j. W smem stride 132 (=4 mod 32): conflict-free.
// ---------------------------------------------------------------------------
__global__ void __launch_bounds__(256, 1) k_xproj(
    const int* __restrict__ x, const int* __restrict__ lengths,
    const float* __restrict__ emb, const float* __restrict__ W_ih,
    const float* __restrict__ b_ih, const float* __restrict__ b_hh)
{
    int b = blockIdx.y;
    int t_base = blockIdx.x * 64;
    int t0 = TT - lengths[b];
    if (t_base + 64 <= t0) return;  // tile entirely before this sequence starts

    extern __shared__ float sm1[];
    float* Ws = sm1;                  // [256][132]
    float* Es = sm1 + 256 * 132;      // [64][132]
    int*   ids = (int*)(Es + 64 * 132);

    int tid = threadIdx.x;
    if (tid < 64) ids[tid] = x[b * TT + t_base + tid];
    for (int idx = tid; idx < 256 * 32; idx += 256) {
        int r = idx >> 5, c4 = idx & 31;
        *(float4*)&Ws[r * 132 + c4 * 4] = *(const float4*)&W_ih[r * EE + c4 * 4];
    }
    __syncthreads();
    for (int idx = tid; idx < 64 * 32; idx += 256) {
        int r = idx >> 5, c4 = idx & 31;
        *(float4*)&Es[r * 132 + c4 * 4] = *(const float4*)&emb[ids[r] * EE + c4 * 4];
    }
    __syncthreads();

    int u = tid & 31;   // lane -> j = u + 32*jj (consecutive lanes, conflict-free W)
    int v = tid >> 5;   // warp -> tokens v*8 .. v*8+7 (broadcast E reads)

    unsigned long long acc[8][8];
    #pragma unroll
    for (int i = 0; i < 8; i++)
        #pragma unroll
        for (int jj = 0; jj < 8; jj++) acc[i][jj] = 0ULL;

    #pragma unroll 1
    for (int k4 = 0; k4 < 32; ++k4) {
        ulonglong2 w[8];
        #pragma unroll
        for (int jj = 0; jj < 8; jj++)
            w[jj] = *(const ulonglong2*)&Ws[(u + 32 * jj) * 132 + k4 * 4];
        #pragma unroll
        for (int i = 0; i < 8; i++) {
            ulonglong2 a = *(const ulonglong2*)&Es[(v * 8 + i) * 132 + k4 * 4];
            #pragma unroll
            for (int jj = 0; jj < 8; jj++) fma2(acc[i][jj], a.x, w[jj].x);
            #pragma unroll
            for (int jj = 0; jj < 8; jj++) fma2(acc[i][jj], a.y, w[jj].y);
        }
    }

    float bsum[8];
    #pragma unroll
    for (int jj = 0; jj < 8; jj++) {
        int j = u + 32 * jj;
        bsum[jj] = b_ih[j] + b_hh[j];
    }
    #pragma unroll
    for (int i = 0; i < 8; i++) {
        int t = t_base + v * 8 + i;
        float* dst = &g_xproj[(b * TT + t) * HH];
        #pragma unroll
        for (int jj = 0; jj < 8; jj++)
            dst[u + 32 * jj] = red2(acc[i][jj]) + bsum[jj];  // coalesced 128B/warp
    }
}

// ---------------------------------------------------------------------------
// Kernel 2: recurrence. One CTA per batch, 256 threads, thread j owns h[j].
// W_hh cols [64,256) live in 96 packed-f32x2 registers/thread (48K regs/SM);
// cols [0,64) in smem with row stride 68 (=4 mod 32 -> conflict-free LDS.128).
// Double-buffered h in smem; ONE barrier per step; starts at t0 = T - len.
// ---------------------------------------------------------------------------
__global__ void __launch_bounds__(256, 1) k_rnn(
    const float* __restrict__ W_hh, const int* __restrict__ lengths)
{
    extern __shared__ float sm2[];
    float* Wsh   = sm2;              // [256][68], cols 0..63
    float* hbuf0 = sm2 + 256 * 68;   // [260]
    float* hbuf1 = hbuf0 + 260;      // [260] (16B-aligned: 260*4 % 16 == 0)

    int b = blockIdx.x;
    int j = threadIdx.x;

    unsigned long long WR[96];  // W_hh[j, 64+2p .. 65+2p]
    {
        const unsigned long long* wrow =
            (const unsigned long long*)(W_hh + j * HH + 64);
        #pragma unroll
        for (int p = 0; p < 96; p++) WR[p] = wrow[p];
    }
    for (int idx = j; idx < 256 * 16; idx += 256) {
        int r = idx >> 4, c4 = idx & 15;
        *(float4*)&Wsh[r * 68 + c4 * 4] = *(const float4*)&W_hh[r * HH + c4 * 4];
    }
    hbuf0[j] = 0.0f;
    hbuf1[j] = 0.0f;
    __syncthreads();

    int len = lengths[b];
    float hfin = 0.0f;
    if (len > 0) {
        int t0 = TT - len;
        const float* xp = g_xproj + (b * TT + t0) * HH + j;
        float xv = *xp;                       // xproj for first step
        float* hc = hbuf0;
        float* hn = hbuf1;
        const ulonglong2* wp = (const ulonglong2*)&Wsh[j * 68];
        for (int t = t0; t < TT; ++t) {
            float xc = xv;
            xv = xp[HH];                      // prefetch next step (array padded)
            const ulonglong2* hp = (const ulonglong2*)hc;
            unsigned long long a0 = 0, a1 = 0, a2 = 0, a3 = 0;
            // k in [0,64): W from smem
            #pragma unroll
            for (int q = 0; q < 16; q += 2) {
                ulonglong2 hA = hp[q], hB = hp[q + 1];
                ulonglong2 wA = wp[q], wB = wp[q + 1];
                fma2(a0, hA.x, wA.x); fma2(a1, hA.y, wA.y);
                fma2(a2, hB.x, wB.x); fma2(a3, hB.y, wB.y);
            }
            // k in [64,256): W from registers
            #pragma unroll
            for (int q = 0; q < 48; q += 2) {
                ulonglong2 hA = hp[16 + q], hB = hp[17 + q];
                fma2(a0, hA.x, WR[2 * q]);     fma2(a1, hA.y, WR[2 * q + 1]);
                fma2(a2, hB.x, WR[2 * q + 2]); fma2(a3, hB.y, WR[2 * q + 3]);
            }
            float s = xc + ((red2(a0) + red2(a1)) + (red2(a2) + red2(a3)));
            hfin = tanh_fast(s);
            hn[j] = hfin;
            __syncthreads();                  // single barrier per step
            float* tmp = hc; hc = hn; hn = tmp;
            xp += HH;
        }
    }
    g_hn[b * HH + j] = hfin;
}

// ---------------------------------------------------------------------------
// Kernel 3: relu(hn @ W0^T + b0). 32 CTAs = 8 b-groups(16) x 4 m-tiles(256);
// W0 traffic amortized over 16 batches (8 MB total).
// ---------------------------------------------------------------------------
__global__ void __launch_bounds__(256, 1) k_mlp1(
    const float* __restrict__ W0, const float* __restrict__ b0)
{
    __shared__ float hs[16 * 256];
    int tid = threadIdx.x;
    int bg = blockIdx.x & 7, mt = blockIdx.x >> 3;
    for (int idx = tid; idx < 16 * 64; idx += 256) {
        int r = idx >> 6, c4 = idx & 63;
        *(float4*)&hs[r * 256 + c4 * 4] =
            *(const float4*)&g_hn[(bg * 16 + r) * HH + c4 * 4];
    }
    __syncthreads();
    int m = mt * 256 + tid;
    unsigned long long accA[16], accB[16];
    #pragma unroll
    for (int r = 0; r < 16; r++) { accA[r] = 0ULL; accB[r] = 0ULL; }
    const float* wrow = W0 + m * HH;
    #pragma unroll 4
    for (int k4 = 0; k4 < 64; k4++) {
        ulonglong2 w = *(const ulonglong2*)&wrow[k4 * 4];
        #pragma unroll
        for (int r = 0; r < 16; r++) {
            ulonglong2 a = *(const ulonglong2*)&hs[r * 256 + k4 * 4];
            fma2(accA[r], a.x, w.x);
            fma2(accB[r], a.y, w.y);
        }
    }
    float bm = b0[m];
    #pragma unroll
    for (int r = 0; r < 16; r++) {
        float s = red2(accA[r]) + red2(accB[r]) + bm;
        g_relu1[(bg * 16 + r) * MM + m] = fmaxf(s, 0.0f);
    }
}

// ---------------------------------------------------------------------------
// Kernel 4: relu(h @ W1^T + b1) then log_softmax over C=5. 1 CTA/batch,
// 5 warps (one per class), warp-shuffle reduction.
// ---------------------------------------------------------------------------
__global__ void k_head(const float* __restrict__ W1, const float* __restrict__ b1,
                       float* __restrict__ out)
{
    __shared__ float logit[8];
    int b = blockIdx.x;
    int tid = threadIdx.x;            // 160 threads = 5 warps
    int c = tid >> 5, lane = tid & 31;
    const float* hr = g_relu1 + b * MM;
    const float* wr = W1 + c * MM;
    float acc = 0.0f;
    for (int k = lane * 4; k < MM; k += 128) {
        float4 a = *(const float4*)&hr[k];
        float4 w = *(const float4*)&wr[k];
        acc += a.x * w.x + a.y * w.y;
        acc += a.z * w.z + a.w * w.w;
    }
    #pragma unroll
    for (int o = 16; o; o >>= 1) acc += __shfl_xor_sync(0xffffffffu, acc, o);
    if (lane == 0) logit[c] = fmaxf(acc + b1[c], 0.0f);
    __syncthreads();
    if (tid < CC) {
        float mx = logit[0];
        #pragma unroll
        for (int i = 1; i < CC; i++) mx = fmaxf(mx, logit[i]);
        float se = 0.0f;
        #pragma unroll
        for (int i = 0; i < CC; i++) se += __expf(logit[i] - mx);
        out[b * CC + tid] = logit[tid] - mx - logf(se);
    }
}

// ---------------------------------------------------------------------------
extern "C" void kernel_launch(void* const* d_in, const int* in_sizes, int n_in,
                              void* d_out, int out_size)
{
    const int*   x    = (const int*)  d_in[0];
    const int*   len  = (const int*)  d_in[1];
    const float* emb  = (const float*)d_in[2];
    const float* W_ih = (const float*)d_in[3];
    const float* W_hh = (const float*)d_in[4];
    const float* b_ih = (const float*)d_in[5];
    const float* b_hh = (const float*)d_in[6];
    const float* W0   = (const float*)d_in[7];
    const float* b0   = (const float*)d_in[8];
    const float* W1   = (const float*)d_in[9];
    const float* b1   = (const float*)d_in[10];
    float* out = (float*)d_out;

    const int smem1 = (256 * 132 + 64 * 132) * 4 + 64 * 4;  // 169,216 B
    const int smem2 = (256 * 68 + 2 * 260) * 4;             //  71,712 B
    cudaFuncSetAttribute(k_xproj, cudaFuncAttributeMaxDynamicSharedMemorySize, smem1);
    cudaFuncSetAttribute(k_rnn,   cudaFuncAttributeMaxDynamicSharedMemorySize, smem2);

    k_xproj<<<dim3(8, 128), 256, smem1>>>(x, len, emb, W_ih, b_ih, b_hh);
    k_rnn<<<128, 256, smem2>>>(W_hh, len);
    k_mlp1<<<32, 256>>>(W0, b0);
    k_head<<<128, 160>>>(W1, b1, out);
}

// round 10
// speedup vs baseline: 1.3849x; 1.3849x over previous
#include <cuda_runtime.h>

#define TT 512
#define BB 128
#define EE 128
#define HH 256
#define MM 1024
#define CC 5

// Scratch (static device globals — no allocation allowed).
// xproj padded by 512 floats so the per-step prefetch can read one row past the end.
__device__ float g_xproj[BB * TT * HH + 512];
__device__ float g_hn[BB * HH];
__device__ float g_relu1[BB * MM];

// ---------------------------------------------------------------------------
// f32x2 packed-FMA helpers (Blackwell FFMA2 path; ptxas won't auto-fuse)
// ---------------------------------------------------------------------------
__device__ __forceinline__ void fma2(unsigned long long& acc,
                                     unsigned long long a,
                                     unsigned long long b) {
    asm("fma.rn.f32x2 %0, %1, %2, %0;" : "+l"(acc) : "l"(a), "l"(b));
}
__device__ __forceinline__ float red2(unsigned long long a) {
    float lo, hi;
    asm("mov.b64 {%0, %1}, %2;" : "=f"(lo), "=f"(hi) : "l"(a));
    return lo + hi;
}
__device__ __forceinline__ float tanh_fast(float x) {
    // (e^{2x}-1)/(e^{2x}+1), clamped so __expf never overflows. abs err ~1e-6.
    float xc = fminf(fmaxf(x, -9.0f), 9.0f);
    float e = __expf(2.0f * xc);
    return __fdividef(e - 1.0f, e + 1.0f);
}

// ---------------------------------------------------------------------------
// Kernel 1: xproj[b,t,j] = emb[x[b,t]] . W_ih[j,:] + b_ih[j] + b_hh[j]
// grid (8 t-tiles of 64, 128 b), 256 thr. Fully-inactive tiles early-exit.
// Thread tile: 8 tokens x 8 j. W smem stride 132 (=4 mod 32): conflict-free.
// ---------------------------------------------------------------------------
__global__ void __launch_bounds__(256, 1) k_xproj(
    const int* __restrict__ x, const int* __restrict__ lengths,
    const float* __restrict__ emb, const float* __restrict__ W_ih,
    const float* __restrict__ b_ih, const float* __restrict__ b_hh)
{
    int b = blockIdx.y;
    int t_base = blockIdx.x * 64;
    int t0 = TT - lengths[b];
    if (t_base + 64 <= t0) return;  // tile entirely before this sequence starts

    extern __shared__ float sm1[];
    float* Ws = sm1;                  // [256][132]
    float* Es = sm1 + 256 * 132;      // [64][132]
    int*   ids = (int*)(Es + 64 * 132);

    int tid = threadIdx.x;
    if (tid < 64) ids[tid] = x[b * TT + t_base + tid];
    for (int idx = tid; idx < 256 * 32; idx += 256) {
        int r = idx >> 5, c4 = idx & 31;
        *(float4*)&Ws[r * 132 + c4 * 4] = *(const float4*)&W_ih[r * EE + c4 * 4];
    }
    __syncthreads();
    for (int idx = tid; idx < 64 * 32; idx += 256) {
        int r = idx >> 5, c4 = idx & 31;
        *(float4*)&Es[r * 132 + c4 * 4] = *(const float4*)&emb[ids[r] * EE + c4 * 4];
    }
    __syncthreads();

    int u = tid & 31;   // lane -> j = u + 32*jj (consecutive lanes, conflict-free W)
    int v = tid >> 5;   // warp -> tokens v*8 .. v*8+7 (broadcast E reads)

    unsigned long long acc[8][8];
    #pragma unroll
    for (int i = 0; i < 8; i++)
        #pragma unroll
        for (int jj = 0; jj < 8; jj++) acc[i][jj] = 0ULL;

    #pragma unroll 1
    for (int k4 = 0; k4 < 32; ++k4) {
        ulonglong2 w[8];
        #pragma unroll
        for (int jj = 0; jj < 8; jj++)
            w[jj] = *(const ulonglong2*)&Ws[(u + 32 * jj) * 132 + k4 * 4];
        #pragma unroll
        for (int i = 0; i < 8; i++) {
            ulonglong2 a = *(const ulonglong2*)&Es[(v * 8 + i) * 132 + k4 * 4];
            #pragma unroll
            for (int jj = 0; jj < 8; jj++) fma2(acc[i][jj], a.x, w[jj].x);
            #pragma unroll
            for (int jj = 0; jj < 8; jj++) fma2(acc[i][jj], a.y, w[jj].y);
        }
    }

    float bsum[8];
    #pragma unroll
    for (int jj = 0; jj < 8; jj++) {
        int j = u + 32 * jj;
        bsum[jj] = b_ih[j] + b_hh[j];
    }
    #pragma unroll
    for (int i = 0; i < 8; i++) {
        int t = t_base + v * 8 + i;
        float* dst = &g_xproj[(b * TT + t) * HH];
        #pragma unroll
        for (int jj = 0; jj < 8; jj++)
            dst[u + 32 * jj] = red2(acc[i][jj]) + bsum[jj];  // coalesced 128B/warp
    }
}

// ---------------------------------------------------------------------------
// Kernel 2: recurrence, k-sliced. One CTA per batch, 256 threads = 8 warps.
// Warp ks owns k-slice [32ks, 32ks+32): it reads ONLY h[32ks..32ks+32)
// (8 broadcast LDS.128/warp/step instead of 64 -> h crossbar 512 -> 64 cyc).
// Lane owns 8 outputs j = lane + 32*o. Per output, k-cols [32ks, 32ks+24)
// live in registers (12 ull x 8 outputs = 192 regs), cols [32ks+24, 32ks+32)
// in smem (2 conflict-free LDS.128, row stride 68 floats = 4 mod 32).
// Partial sums reduced via psum[8][264] smem stage; thread j adds xproj,
// applies tanh, writes h. Two barriers per step.
// ---------------------------------------------------------------------------
__global__ void __launch_bounds__(256, 1) k_rnn(
    const float* __restrict__ W_hh, const int* __restrict__ lengths)
{
    extern __shared__ float sm2[];
    float* Wsh  = sm2;               // [256][68]: row j, slice s cols [32s+24,32s+32) at +8s
    float* psum = sm2 + 256 * 68;    // [8][264] (stride 264 = 8 mod 32)
    float* hbuf = psum + 8 * 264;    // [264], 16B-aligned

    int b = blockIdx.x;
    int tid = threadIdx.x;
    int ks = tid >> 5;               // warp = k-slice
    int l = tid & 31;

    // W register part: 8 outputs (j = l + 32o), 12 ull (24 k-cols) each
    unsigned long long WR[96];
    #pragma unroll
    for (int o = 0; o < 8; o++) {
        const unsigned long long* src =
            (const unsigned long long*)(W_hh + (l + 32 * o) * HH + ks * 32);
        #pragma unroll
        for (int p = 0; p < 12; p++) WR[o * 12 + p] = src[p];
    }
    // smem W fill: row r, slice s, cols [32s+24, 32s+32) -> Wsh[r*68 + 8s ..]
    for (int idx = tid; idx < 256 * 16; idx += 256) {
        int r = idx >> 4, f = idx & 15;   // f = 2s + q
        int s = f >> 1, q = f & 1;
        *(float4*)&Wsh[r * 68 + f * 4] =
            *(const float4*)&W_hh[r * HH + s * 32 + 24 + q * 4];
    }
    hbuf[tid] = 0.0f;
    __syncthreads();

    int len = lengths[b];
    float hfin = 0.0f;
    if (len > 0) {
        int t0 = TT - len;
        const float* xp = g_xproj + (b * TT + t0) * HH + tid;
        float xv = *xp;                                   // xproj for first step
        const ulonglong2* hs = (const ulonglong2*)(hbuf + ks * 32);
        const float* wsp = Wsh + l * 68 + ks * 8;
        float* ps = psum + ks * 264 + l;
        const float* rp = psum + tid;
        for (int t = t0; t < TT; ++t) {
            unsigned long long acc[8];
            #pragma unroll
            for (int o = 0; o < 8; o++) acc[o] = 0ULL;
            // k-pairs 0..11 of this slice: W from registers, h broadcast LDS
            #pragma unroll
            for (int c = 0; c < 6; c++) {
                ulonglong2 hv = hs[c];
                #pragma unroll
                for (int o = 0; o < 8; o++) {
                    fma2(acc[o], hv.x, WR[o * 12 + 2 * c]);
                    fma2(acc[o], hv.y, WR[o * 12 + 2 * c + 1]);
                }
            }
            // k-pairs 12..15: W from smem (2 LDS.128 per output)
            ulonglong2 h6 = hs[6], h7 = hs[7];
            #pragma unroll
            for (int o = 0; o < 8; o++) {
                ulonglong2 w0 = *(const ulonglong2*)(wsp + o * (32 * 68));
                ulonglong2 w1 = *(const ulonglong2*)(wsp + o * (32 * 68) + 4);
                fma2(acc[o], h6.x, w0.x); fma2(acc[o], h6.y, w0.y);
                fma2(acc[o], h7.x, w1.x); fma2(acc[o], h7.y, w1.y);
            }
            // partials for this slice (coalesced STS.32)
            #pragma unroll
            for (int o = 0; o < 8; o++) ps[o * 32] = red2(acc[o]);
            __syncthreads();
            // reduce stage: thread j = tid sums 8 slice partials + xproj
            float xc = xv;
            xv = xp[HH];                                  // prefetch (padded array)
            float p0 = rp[0 * 264], p1 = rp[1 * 264];
            float p2 = rp[2 * 264], p3 = rp[3 * 264];
            float p4 = rp[4 * 264], p5 = rp[5 * 264];
            float p6 = rp[6 * 264], p7 = rp[7 * 264];
            float s = xc + (((p0 + p1) + (p2 + p3)) + ((p4 + p5) + (p6 + p7)));
            hfin = tanh_fast(s);
            hbuf[tid] = hfin;
            __syncthreads();
            xp += HH;
        }
    }
    g_hn[b * HH + tid] = hfin;
}

// ---------------------------------------------------------------------------
// Kernel 3: relu(hn @ W0^T + b0). 32 CTAs = 8 b-groups(16) x 4 m-tiles(256);
// W0 traffic amortized over 16 batches (8 MB total).
// ---------------------------------------------------------------------------
__global__ void __launch_bounds__(256, 1) k_mlp1(
    const float* __restrict__ W0, const float* __restrict__ b0)
{
    __shared__ float hs[16 * 256];
    int tid = threadIdx.x;
    int bg = blockIdx.x & 7, mt = blockIdx.x >> 3;
    for (int idx = tid; idx < 16 * 64; idx += 256) {
        int r = idx >> 6, c4 = idx & 63;
        *(float4*)&hs[r * 256 + c4 * 4] =
            *(const float4*)&g_hn[(bg * 16 + r) * HH + c4 * 4];
    }
    __syncthreads();
    int m = mt * 256 + tid;
    unsigned long long accA[16], accB[16];
    #pragma unroll
    for (int r = 0; r < 16; r++) { accA[r] = 0ULL; accB[r] = 0ULL; }
    const float* wrow = W0 + m * HH;
    #pragma unroll 4
    for (int k4 = 0; k4 < 64; k4++) {
        ulonglong2 w = *(const ulonglong2*)&wrow[k4 * 4];
        #pragma unroll
        for (int r = 0; r < 16; r++) {
            ulonglong2 a = *(const ulonglong2*)&hs[r * 256 + k4 * 4];
            fma2(accA[r], a.x, w.x);
            fma2(accB[r], a.y, w.y);
        }
    }
    float bm = b0[m];
    #pragma unroll
    for (int r = 0; r < 16; r++) {
        float s = red2(accA[r]) + red2(accB[r]) + bm;
        g_relu1[(bg * 16 + r) * MM + m] = fmaxf(s, 0.0f);
    }
}

// ---------------------------------------------------------------------------
// Kernel 4: relu(h @ W1^T + b1) then log_softmax over C=5. 1 CTA/batch,
// 5 warps (one per class), warp-shuffle reduction.
// ---------------------------------------------------------------------------
__global__ void k_head(const float* __restrict__ W1, const float* __restrict__ b1,
                       float* __restrict__ out)
{
    __shared__ float logit[8];
    int b = blockIdx.x;
    int tid = threadIdx.x;            // 160 threads = 5 warps
    int c = tid >> 5, lane = tid & 31;
    const float* hr = g_relu1 + b * MM;
    const float* wr = W1 + c * MM;
    float acc = 0.0f;
    for (int k = lane * 4; k < MM; k += 128) {
        float4 a = *(const float4*)&hr[k];
        float4 w = *(const float4*)&wr[k];
        acc += a.x * w.x + a.y * w.y;
        acc += a.z * w.z + a.w * w.w;
    }
    #pragma unroll
    for (int o = 16; o; o >>= 1) acc += __shfl_xor_sync(0xffffffffu, acc, o);
    if (lane == 0) logit[c] = fmaxf(acc + b1[c], 0.0f);
    __syncthreads();
    if (tid < CC) {
        float mx = logit[0];
        #pragma unroll
        for (int i = 1; i < CC; i++) mx = fmaxf(mx, logit[i]);
        float se = 0.0f;
        #pragma unroll
        for (int i = 0; i < CC; i++) se += __expf(logit[i] - mx);
        out[b * CC + tid] = logit[tid] - mx - logf(se);
    }
}

// ---------------------------------------------------------------------------
extern "C" void kernel_launch(void* const* d_in, const int* in_sizes, int n_in,
                              void* d_out, int out_size)
{
    const int*   x    = (const int*)  d_in[0];
    const int*   len  = (const int*)  d_in[1];
    const float* emb  = (const float*)d_in[2];
    const float* W_ih = (const float*)d_in[3];
    const float* W_hh = (const float*)d_in[4];
    const float* b_ih = (const float*)d_in[5];
    const float* b_hh = (const float*)d_in[6];
    const float* W0   = (const float*)d_in[7];
    const float* b0   = (const float*)d_in[8];
    const float* W1   = (const float*)d_in[9];
    const float* b1   = (const float*)d_in[10];
    float* out = (float*)d_out;

    const int smem1 = (256 * 132 + 64 * 132) * 4 + 64 * 4;        // 169,216 B
    const int smem2 = (256 * 68 + 8 * 264 + 264) * 4;             //  79,136 B
    cudaFuncSetAttribute(k_xproj, cudaFuncAttributeMaxDynamicSharedMemorySize, smem1);
    cudaFuncSetAttribute(k_rnn,   cudaFuncAttributeMaxDynamicSharedMemorySize, smem2);

    k_xproj<<<dim3(8, 128), 256, smem1>>>(x, len, emb, W_ih, b_ih, b_hh);
    k_rnn<<<128, 256, smem2>>>(W_hh, len);
    k_mlp1<<<32, 256>>>(W0, b0);
    k_head<<<128, 160>>>(W1, b1, out);
}